// round 1
// baseline (speedup 1.0000x reference)
#include <cuda_runtime.h>
#include <math.h>

#define B_   4
#define S_   1024
#define D_   2048
#define NH_  16
#define NKV_ 8
#define HD_  128
#define NREP_ 2
#define K_   8
#define FFN_ 5632
#define V_   32000
#define LAT_ 1024
#define HID_ 2048
#define EPS_ 1e-5f

// ---------------- scratch (device globals; allocation-free) ----------------
__device__ float g_h   [B_*S_*D_];
__device__ float g_x   [B_*S_*D_];
__device__ float g_q   [B_*S_*D_];
__device__ float g_k   [B_*S_*NKV_*HD_];
__device__ float g_v   [B_*S_*NKV_*HD_];
__device__ float g_attn[B_*S_*D_];
__device__ float g_sc  [(size_t)B_*NH_*S_*S_];   // 256 MB score scratch
__device__ float g_f1  [B_*S_*FFN_];
__device__ float g_f3  [B_*S_*FFN_];
__device__ float g_h1  [B_*HID_];
__device__ float g_spec[B_*K_*D_];

// ---------------- block reductions ----------------
__device__ __forceinline__ float blockReduceSum(float v) {
    __shared__ float sh[32];
    __syncthreads();
    int lane = threadIdx.x & 31, wid = threadIdx.x >> 5;
    #pragma unroll
    for (int o = 16; o; o >>= 1) v += __shfl_down_sync(0xffffffffu, v, o);
    if (lane == 0) sh[wid] = v;
    __syncthreads();
    int nw = (blockDim.x + 31) >> 5;
    v = (threadIdx.x < nw) ? sh[threadIdx.x] : 0.f;
    if (wid == 0) {
        #pragma unroll
        for (int o = 16; o; o >>= 1) v += __shfl_down_sync(0xffffffffu, v, o);
        if (lane == 0) sh[0] = v;
    }
    __syncthreads();
    return sh[0];
}

__device__ __forceinline__ float blockReduceMax(float v) {
    __shared__ float sh[32];
    __syncthreads();
    int lane = threadIdx.x & 31, wid = threadIdx.x >> 5;
    #pragma unroll
    for (int o = 16; o; o >>= 1) v = fmaxf(v, __shfl_down_sync(0xffffffffu, v, o));
    if (lane == 0) sh[wid] = v;
    __syncthreads();
    int nw = (blockDim.x + 31) >> 5;
    v = (threadIdx.x < nw) ? sh[threadIdx.x] : -3.4e38f;
    if (wid == 0) {
        #pragma unroll
        for (int o = 16; o; o >>= 1) v = fmaxf(v, __shfl_down_sync(0xffffffffu, v, o));
        if (lane == 0) sh[0] = v;
    }
    __syncthreads();
    return sh[0];
}

// ---------------- generic strided-batched SGEMM ----------------
// C = alpha*(A @ B(^T)) [+bias] [gelu] [+C]
// A: M x Kd (lda), B: Kd x N (ldb) or N x Kd if transB, C: M x N (ldc).
// batch z: b1=z/nb2, b2=z%nb2; A += b1*sA1+b2*sA2; B += b1*sB1+(b2/bDiv)*sB2; C += b1*sC1+b2*sC2
#define BM 64
#define BN 64
#define BKK 16
__global__ void __launch_bounds__(256)
gemm_kernel(const float* __restrict__ A, const float* __restrict__ B,
            float* __restrict__ C, const float* __restrict__ bias,
            int M, int N, int Kd, int lda, int ldb, int ldc,
            long long sA1, long long sA2, long long sB1, long long sB2,
            long long sC1, long long sC2,
            int nb2, int bDiv, float alpha, int act, int accum, int transB)
{
    int z = blockIdx.z;
    int b1 = z / nb2, b2 = z % nb2;
    A += (size_t)b1 * sA1 + (size_t)b2 * sA2;
    B += (size_t)b1 * sB1 + (size_t)(b2 / bDiv) * sB2;
    C += (size_t)b1 * sC1 + (size_t)b2 * sC2;

    __shared__ float As[BKK][BM + 1];
    __shared__ float Bs[BKK][BN + 1];

    int tid = threadIdx.x;
    int tx = tid & 15, ty = tid >> 4;
    int m0 = blockIdx.y * BM, n0 = blockIdx.x * BN;

    float acc[4][4] = {};

    for (int k0 = 0; k0 < Kd; k0 += BKK) {
        #pragma unroll
        for (int i = 0; i < 4; i++) {
            int idx = tid + i * 256;        // 64x16 A tile
            int r = idx >> 4, c = idx & 15;
            int gm = m0 + r, gk = k0 + c;
            As[c][r] = (gm < M && gk < Kd) ? A[(size_t)gm * lda + gk] : 0.f;
        }
        if (!transB) {
            #pragma unroll
            for (int i = 0; i < 4; i++) {
                int idx = tid + i * 256;    // 16x64 B tile
                int r = idx >> 6, c = idx & 63;
                int gk = k0 + r, gn = n0 + c;
                Bs[r][c] = (gk < Kd && gn < N) ? B[(size_t)gk * ldb + gn] : 0.f;
            }
        } else {
            #pragma unroll
            for (int i = 0; i < 4; i++) {
                int idx = tid + i * 256;    // 64x16 (N x K) tile
                int nn = idx >> 4, kk = idx & 15;
                int gn = n0 + nn, gk = k0 + kk;
                Bs[kk][nn] = (gn < N && gk < Kd) ? B[(size_t)gn * ldb + gk] : 0.f;
            }
        }
        __syncthreads();
        #pragma unroll
        for (int kk = 0; kk < BKK; kk++) {
            float a[4], b[4];
            #pragma unroll
            for (int i = 0; i < 4; i++) a[i] = As[kk][ty * 4 + i];
            #pragma unroll
            for (int j = 0; j < 4; j++) b[j] = Bs[kk][tx * 4 + j];
            #pragma unroll
            for (int i = 0; i < 4; i++)
                #pragma unroll
                for (int j = 0; j < 4; j++)
                    acc[i][j] += a[i] * b[j];
        }
        __syncthreads();
    }

    #pragma unroll
    for (int i = 0; i < 4; i++) {
        int gm = m0 + ty * 4 + i;
        if (gm >= M) continue;
        #pragma unroll
        for (int j = 0; j < 4; j++) {
            int gn = n0 + tx * 4 + j;
            if (gn >= N) continue;
            float vv = acc[i][j] * alpha;
            if (bias) vv += bias[gn];
            if (act == 1) vv = 0.5f * vv * (1.f + erff(vv * 0.70710678118654752f));
            size_t ci = (size_t)gm * ldc + gn;
            if (accum) vv += C[ci];
            C[ci] = vv;
        }
    }
}

// ---------------- elementwise / norm kernels ----------------
__global__ void rmsnorm_kernel(const float* __restrict__ x, const float* __restrict__ w,
                               float* __restrict__ out) {
    size_t row = blockIdx.x;
    const float* xr = x + row * D_;
    float* o = out + row * D_;
    float s = 0.f;
    for (int i = threadIdx.x; i < D_; i += blockDim.x) { float v = xr[i]; s += v * v; }
    s = blockReduceSum(s);
    float inv = rsqrtf(s / (float)D_ + EPS_);
    for (int i = threadIdx.x; i < D_; i += blockDim.x) o[i] = xr[i] * inv * w[i];
}

__global__ void layernorm_kernel(float* __restrict__ x, const float* __restrict__ g,
                                 const float* __restrict__ b) {
    size_t row = blockIdx.x;
    float* xr = x + row * D_;
    float s = 0.f;
    for (int i = threadIdx.x; i < D_; i += blockDim.x) s += xr[i];
    s = blockReduceSum(s);
    float mu = s / (float)D_;
    float s2 = 0.f;
    for (int i = threadIdx.x; i < D_; i += blockDim.x) { float d = xr[i] - mu; s2 += d * d; }
    s2 = blockReduceSum(s2);
    float inv = rsqrtf(s2 / (float)D_ + EPS_);
    for (int i = threadIdx.x; i < D_; i += blockDim.x)
        xr[i] = (xr[i] - mu) * inv * g[i] + b[i];
}

__global__ void embed_kernel(const int* __restrict__ ids, const int* __restrict__ pos,
                             const float* __restrict__ tok_emb, const float* __restrict__ spec,
                             float* __restrict__ h) {
    int bs = blockIdx.x;
    int b = bs / S_, s = bs % S_;
    int p = pos[b];
    const float* src;
    if (s >= p && s < p + K_) src = spec + ((size_t)b * K_ + (s - p)) * D_;
    else                      src = tok_emb + (size_t)ids[bs] * D_;
    float* dst = h + (size_t)bs * D_;
    for (int i = threadIdx.x; i < D_; i += blockDim.x) dst[i] = src[i];
}

__global__ void rope_kernel(float* __restrict__ x, int nheads, size_t total) {
    size_t idx = (size_t)blockIdx.x * blockDim.x + threadIdx.x;
    if (idx >= total) return;
    int i = (int)(idx & (HD_ / 2 - 1));
    size_t t = idx >> 6;                 // / (HD/2)
    int s = (int)((t / nheads) % S_);
    float freq = expf(((float)(2 * i) / (float)HD_) * -9.210340371976184f); // -ln(1e4)
    float ang = (float)s * freq;
    float sn, cs; sincosf(ang, &sn, &cs);
    size_t off = (t << 7) + 2 * i;       // t*HD + 2i
    float xr = x[off], xi = x[off + 1];
    x[off]     = xr * cs - xi * sn;
    x[off + 1] = xr * sn + xi * cs;
}

__global__ void softmax_causal_kernel(float* __restrict__ sc) {
    size_t row = blockIdx.x;             // (b*NH + h)*S + q
    int q = (int)(row % S_);
    float* r = sc + row * (size_t)S_;
    int n = q + 1;
    float mx = -3.4e38f;
    for (int j = threadIdx.x; j < n; j += blockDim.x) mx = fmaxf(mx, r[j]);
    mx = blockReduceMax(mx);
    float sum = 0.f;
    for (int j = threadIdx.x; j < n; j += blockDim.x) {
        float e = expf(r[j] - mx);
        r[j] = e; sum += e;
    }
    sum = blockReduceSum(sum);
    float inv = 1.f / sum;
    for (int j = threadIdx.x; j < n; j += blockDim.x) r[j] *= inv;
    for (int j = n + threadIdx.x; j < S_; j += blockDim.x) r[j] = 0.f;
}

__global__ void silu_mul_kernel(float* __restrict__ a, const float* __restrict__ c, size_t n) {
    size_t i = (size_t)blockIdx.x * blockDim.x + threadIdx.x;
    if (i >= n) return;
    float xv = a[i];
    a[i] = (xv / (1.f + expf(-xv))) * c[i];
}

// ---------------- host side ----------------
static inline void gemm_nb(const float* A, const float* Bm, float* C, const float* bias,
                           int M, int N, int Kd, int lda, int ldb, int ldc,
                           float alpha, int act, int accum) {
    dim3 grid((N + BN - 1) / BN, (M + BM - 1) / BM, 1);
    gemm_kernel<<<grid, 256>>>(A, Bm, C, bias, M, N, Kd, lda, ldb, ldc,
                               0, 0, 0, 0, 0, 0, 1, 1, alpha, act, accum, 0);
}

extern "C" void kernel_launch(void* const* d_in, const int* in_sizes, int n_in,
                              void* d_out, int out_size) {
    const int*   input_ids = (const int*)  d_in[0];
    const float* spectra   = (const float*)d_in[1];
    const int*   spos      = (const int*)  d_in[2];
    const float* proj_w1   = (const float*)d_in[3];
    const float* proj_b1   = (const float*)d_in[4];
    const float* proj_w2   = (const float*)d_in[5];
    const float* proj_b2   = (const float*)d_in[6];
    const float* proj_ln_g = (const float*)d_in[7];
    const float* proj_ln_b = (const float*)d_in[8];
    const float* tok_emb   = (const float*)d_in[9];
    const float* attn_norm = (const float*)d_in[10];
    const float* wq        = (const float*)d_in[11];
    const float* wk        = (const float*)d_in[12];
    const float* wv        = (const float*)d_in[13];
    const float* wo        = (const float*)d_in[14];
    const float* ffn_norm  = (const float*)d_in[15];
    const float* w1        = (const float*)d_in[16];
    const float* w3        = (const float*)d_in[17];
    const float* w2        = (const float*)d_in[18];
    const float* norm_w    = (const float*)d_in[19];
    const float* out_w     = (const float*)d_in[20];
    float* out = (float*)d_out;

    float *h, *x, *q, *k, *v, *attn, *sc, *f1, *f3, *h1, *spec;
    cudaGetSymbolAddress((void**)&h,    g_h);
    cudaGetSymbolAddress((void**)&x,    g_x);
    cudaGetSymbolAddress((void**)&q,    g_q);
    cudaGetSymbolAddress((void**)&k,    g_k);
    cudaGetSymbolAddress((void**)&v,    g_v);
    cudaGetSymbolAddress((void**)&attn, g_attn);
    cudaGetSymbolAddress((void**)&sc,   g_sc);
    cudaGetSymbolAddress((void**)&f1,   g_f1);
    cudaGetSymbolAddress((void**)&f3,   g_f3);
    cudaGetSymbolAddress((void**)&h1,   g_h1);
    cudaGetSymbolAddress((void**)&spec, g_spec);

    // ---- spectral projection: gelu(spectra@W1+b1) @ W2 + b2, then LayerNorm ----
    gemm_nb(spectra, proj_w1, h1, proj_b1, B_, HID_, LAT_, LAT_, HID_, HID_, 1.f, 1, 0);
    gemm_nb(h1, proj_w2, spec, proj_b2, B_, K_*D_, HID_, HID_, K_*D_, K_*D_, 1.f, 0, 0);
    layernorm_kernel<<<B_*K_, 256>>>(spec, proj_ln_g, proj_ln_b);

    // ---- embedding + spectral token scatter ----
    embed_kernel<<<B_*S_, 256>>>(input_ids, spos, tok_emb, spec, h);

    const float inv_sqrt_hd = 0.08838834764831845f;

    for (int l = 0; l < 2; l++) {
        const float* Wq = wq + (size_t)l * D_ * (NH_ * HD_);
        const float* Wk = wk + (size_t)l * D_ * (NKV_ * HD_);
        const float* Wv = wv + (size_t)l * D_ * (NKV_ * HD_);
        const float* Wo = wo + (size_t)l * (NH_ * HD_) * D_;
        const float* W1 = w1 + (size_t)l * D_ * FFN_;
        const float* W3 = w3 + (size_t)l * D_ * FFN_;
        const float* W2 = w2 + (size_t)l * FFN_ * D_;

        rmsnorm_kernel<<<B_*S_, 256>>>(h, attn_norm + (size_t)l * D_, x);

        gemm_nb(x, Wq, q, nullptr, B_*S_, NH_*HD_,  D_, D_, NH_*HD_,  NH_*HD_,  1.f, 0, 0);
        gemm_nb(x, Wk, k, nullptr, B_*S_, NKV_*HD_, D_, D_, NKV_*HD_, NKV_*HD_, 1.f, 0, 0);
        gemm_nb(x, Wv, v, nullptr, B_*S_, NKV_*HD_, D_, D_, NKV_*HD_, NKV_*HD_, 1.f, 0, 0);

        {
            size_t np = (size_t)B_ * S_ * NH_ * (HD_ / 2);
            rope_kernel<<<(unsigned)((np + 255) / 256), 256>>>(q, NH_, np);
            np = (size_t)B_ * S_ * NKV_ * (HD_ / 2);
            rope_kernel<<<(unsigned)((np + 255) / 256), 256>>>(k, NKV_, np);
        }

        // scores[b,h] = (1/sqrt(HD)) * Q_bh (S x HD) @ K_bh^T
        {
            dim3 grid(S_/BN, S_/BM, B_*NH_);
            gemm_kernel<<<grid, 256>>>(q, k, sc, nullptr,
                S_, S_, HD_,
                D_, NKV_*HD_, S_,
                (long long)S_*D_,        (long long)HD_,
                (long long)S_*NKV_*HD_,  (long long)HD_,
                (long long)NH_*S_*S_,    (long long)S_*S_,
                NH_, NREP_, inv_sqrt_hd, 0, 0, 1);
        }

        softmax_causal_kernel<<<B_*NH_*S_, 128>>>(sc);

        // attn[b,:,h,:] = P_bh (S x S) @ V_bh (S x HD)
        {
            dim3 grid(HD_/BN, S_/BM, B_*NH_);
            gemm_kernel<<<grid, 256>>>(sc, v, attn, nullptr,
                S_, HD_, S_,
                S_, NKV_*HD_, D_,
                (long long)NH_*S_*S_,    (long long)S_*S_,
                (long long)S_*NKV_*HD_,  (long long)HD_,
                (long long)S_*D_,        (long long)HD_,
                NH_, NREP_, 1.f, 0, 0, 0);
        }

        // h += attn @ Wo
        gemm_nb(attn, Wo, h, nullptr, B_*S_, D_, D_, D_, D_, D_, 1.f, 0, 1);

        // FFN
        rmsnorm_kernel<<<B_*S_, 256>>>(h, ffn_norm + (size_t)l * D_, x);
        gemm_nb(x, W1, f1, nullptr, B_*S_, FFN_, D_, D_, FFN_, FFN_, 1.f, 0, 0);
        gemm_nb(x, W3, f3, nullptr, B_*S_, FFN_, D_, D_, FFN_, FFN_, 1.f, 0, 0);
        {
            size_t n = (size_t)B_ * S_ * FFN_;
            silu_mul_kernel<<<(unsigned)((n + 255) / 256), 256>>>(f1, f3, n);
        }
        // h += (silu(g1)*g3) @ W2
        gemm_nb(f1, W2, h, nullptr, B_*S_, D_, FFN_, FFN_, D_, D_, 1.f, 0, 1);
    }

    // ---- final norm + logits ----
    rmsnorm_kernel<<<B_*S_, 256>>>(h, norm_w, x);
    gemm_nb(x, out_w, out, nullptr, B_*S_, V_, D_, D_, V_, V_, 1.f, 0, 0);
}

// round 3
// speedup vs baseline: 2.9686x; 2.9686x over previous
#include <cuda_runtime.h>
#include <cuda_bf16.h>
#include <stdint.h>
#include <math.h>

#define B_   4
#define S_   1024
#define D_   2048
#define NH_  16
#define NKV_ 8
#define HD_  128
#define NREP_ 2
#define K_   8
#define FFN_ 5632
#define V_   32000
#define LAT_ 1024
#define HID_ 2048
#define EPS_ 1e-5f

// ---------------- scratch (device globals; allocation-free) ----------------
__device__ float g_h   [B_*S_*D_];
__device__ float g_x   [B_*S_*D_];
__device__ float g_q   [B_*S_*D_];
__device__ float g_k   [B_*S_*NKV_*HD_];
__device__ float g_v   [B_*S_*NKV_*HD_];
__device__ float g_attn[B_*S_*D_];
__device__ float g_sc  [(size_t)B_*NH_*S_*S_];   // 256 MB score scratch
__device__ float g_f1  [B_*S_*FFN_];
__device__ float g_f3  [B_*S_*FFN_];
__device__ float g_h1  [B_*HID_];
__device__ float g_spec[B_*K_*D_];

// ---------------- block reductions ----------------
__device__ __forceinline__ float blockReduceSum(float v) {
    __shared__ float sh[32];
    __syncthreads();
    int lane = threadIdx.x & 31, wid = threadIdx.x >> 5;
    #pragma unroll
    for (int o = 16; o; o >>= 1) v += __shfl_down_sync(0xffffffffu, v, o);
    if (lane == 0) sh[wid] = v;
    __syncthreads();
    int nw = (blockDim.x + 31) >> 5;
    v = (threadIdx.x < nw) ? sh[threadIdx.x] : 0.f;
    if (wid == 0) {
        #pragma unroll
        for (int o = 16; o; o >>= 1) v += __shfl_down_sync(0xffffffffu, v, o);
        if (lane == 0) sh[0] = v;
    }
    __syncthreads();
    return sh[0];
}

__device__ __forceinline__ float blockReduceMax(float v) {
    __shared__ float sh[32];
    __syncthreads();
    int lane = threadIdx.x & 31, wid = threadIdx.x >> 5;
    #pragma unroll
    for (int o = 16; o; o >>= 1) v = fmaxf(v, __shfl_down_sync(0xffffffffu, v, o));
    if (lane == 0) sh[wid] = v;
    __syncthreads();
    int nw = (blockDim.x + 31) >> 5;
    v = (threadIdx.x < nw) ? sh[threadIdx.x] : -3.4e38f;
    if (wid == 0) {
        #pragma unroll
        for (int o = 16; o; o >>= 1) v = fmaxf(v, __shfl_down_sync(0xffffffffu, v, o));
        if (lane == 0) sh[0] = v;
    }
    __syncthreads();
    return sh[0];
}

// ================= bf16-split tensor-core GEMM =================
// C = alpha*(A @ B(^T)) [+bias] [gelu] [+C], fp32 in/out, bf16 hi/lo split
// on the tensor pipe: C += Ah*Bh + Ah*Bl + Al*Bh  (error ~2^-17 per product).
// Block tile 128x128x32, 256 threads (8 warps, 2x4), warp tile 64x32.
#define BM 128
#define BN 128
#define BK 32
#define LDA_S 34   // padded smem leading dim (bf16 units), conflict-free

#define MMA_BF16(d, a, b)                                                          \
    asm volatile("mma.sync.aligned.m16n8k16.row.col.f32.bf16.bf16.f32 "            \
                 "{%0,%1,%2,%3},{%4,%5,%6,%7},{%8,%9},{%0,%1,%2,%3};"              \
                 : "+f"(d[0]), "+f"(d[1]), "+f"(d[2]), "+f"(d[3])                  \
                 : "r"(a[0]), "r"(a[1]), "r"(a[2]), "r"(a[3]), "r"(b[0]), "r"(b[1]))

__global__ void __launch_bounds__(256)
gemm_kernel(const float* __restrict__ A, const float* __restrict__ B,
            float* __restrict__ C, const float* __restrict__ bias,
            int M, int N, int Kd, int lda, int ldb, int ldc,
            long long sA1, long long sA2, long long sB1, long long sB2,
            long long sC1, long long sC2,
            int nb2, int bDiv, float alpha, int act, int accum, int transB)
{
    int z = blockIdx.z;
    int b1 = z / nb2, b2 = z % nb2;
    A += (size_t)b1 * sA1 + (size_t)b2 * sA2;
    B += (size_t)b1 * sB1 + (size_t)(b2 / bDiv) * sB2;
    C += (size_t)b1 * sC1 + (size_t)b2 * sC2;

    __shared__ __nv_bfloat16 Ash[BM * LDA_S];
    __shared__ __nv_bfloat16 Asl[BM * LDA_S];
    __shared__ __nv_bfloat16 Bsh[BN * LDA_S];
    __shared__ __nv_bfloat16 Bsl[BN * LDA_S];

    int tid  = threadIdx.x;
    int lane = tid & 31;
    int warp = tid >> 5;
    int wm = warp >> 2;          // 0..1
    int wn = warp & 3;           // 0..3
    int m0 = blockIdx.y * BM, n0 = blockIdx.x * BN;

    float c[4][4][4];
    #pragma unroll
    for (int i = 0; i < 4; i++)
        #pragma unroll
        for (int j = 0; j < 4; j++)
            #pragma unroll
            for (int t = 0; t < 4; t++) c[i][j][t] = 0.f;

    for (int k0 = 0; k0 < Kd; k0 += BK) {
        // ---- load A tile [BM][BK] (row-major, coalesced along k) ----
        #pragma unroll
        for (int i = 0; i < 16; i++) {
            int idx = tid + i * 256;          // BM*BK/256 = 16
            int kk = idx & 31, r = idx >> 5;
            int gm = m0 + r, gk = k0 + kk;
            float v = (gm < M && gk < Kd) ? A[(size_t)gm * lda + gk] : 0.f;
            __nv_bfloat16 hi = __float2bfloat16(v);
            __nv_bfloat16 lo = __float2bfloat16(v - __bfloat162float(hi));
            Ash[r * LDA_S + kk] = hi;
            Asl[r * LDA_S + kk] = lo;
        }
        // ---- load B tile into [BN][BK] (n-major rows) ----
        if (!transB) {
            #pragma unroll
            for (int i = 0; i < 16; i++) {
                int idx = tid + i * 256;
                int kk = idx >> 7, nn = idx & 127;   // coalesced along n
                int gk = k0 + kk, gn = n0 + nn;
                float v = (gk < Kd && gn < N) ? B[(size_t)gk * ldb + gn] : 0.f;
                __nv_bfloat16 hi = __float2bfloat16(v);
                __nv_bfloat16 lo = __float2bfloat16(v - __bfloat162float(hi));
                Bsh[nn * LDA_S + kk] = hi;
                Bsl[nn * LDA_S + kk] = lo;
            }
        } else {
            #pragma unroll
            for (int i = 0; i < 16; i++) {
                int idx = tid + i * 256;
                int kk = idx & 31, nn = idx >> 5;    // coalesced along k
                int gn = n0 + nn, gk = k0 + kk;
                float v = (gn < N && gk < Kd) ? B[(size_t)gn * ldb + gk] : 0.f;
                __nv_bfloat16 hi = __float2bfloat16(v);
                __nv_bfloat16 lo = __float2bfloat16(v - __bfloat162float(hi));
                Bsh[nn * LDA_S + kk] = hi;
                Bsl[nn * LDA_S + kk] = lo;
            }
        }
        __syncthreads();

        #pragma unroll
        for (int s = 0; s < 2; s++) {                 // two k16 sub-steps
            int kc = s * 16 + (lane & 3) * 2;
            unsigned int ah[4][4], al[4][4], bh[4][2], bl[4][2];
            #pragma unroll
            for (int mt = 0; mt < 4; mt++) {
                int row = wm * 64 + mt * 16 + (lane >> 2);
                const __nv_bfloat16* ph = &Ash[row * LDA_S + kc];
                const __nv_bfloat16* pl = &Asl[row * LDA_S + kc];
                ah[mt][0] = *(const unsigned int*)(ph);
                ah[mt][1] = *(const unsigned int*)(ph + 8 * LDA_S);
                ah[mt][2] = *(const unsigned int*)(ph + 8);
                ah[mt][3] = *(const unsigned int*)(ph + 8 * LDA_S + 8);
                al[mt][0] = *(const unsigned int*)(pl);
                al[mt][1] = *(const unsigned int*)(pl + 8 * LDA_S);
                al[mt][2] = *(const unsigned int*)(pl + 8);
                al[mt][3] = *(const unsigned int*)(pl + 8 * LDA_S + 8);
            }
            #pragma unroll
            for (int nt = 0; nt < 4; nt++) {
                int nrow = wn * 32 + nt * 8 + (lane >> 2);
                const __nv_bfloat16* ph = &Bsh[nrow * LDA_S + kc];
                const __nv_bfloat16* pl = &Bsl[nrow * LDA_S + kc];
                bh[nt][0] = *(const unsigned int*)(ph);
                bh[nt][1] = *(const unsigned int*)(ph + 8);
                bl[nt][0] = *(const unsigned int*)(pl);
                bl[nt][1] = *(const unsigned int*)(pl + 8);
            }
            #pragma unroll
            for (int mt = 0; mt < 4; mt++)
                #pragma unroll
                for (int nt = 0; nt < 4; nt++) {
                    MMA_BF16(c[mt][nt], ah[mt], bh[nt]);
                    MMA_BF16(c[mt][nt], ah[mt], bl[nt]);
                    MMA_BF16(c[mt][nt], al[mt], bh[nt]);
                }
        }
        __syncthreads();
    }

    // ---- epilogue ----
    #pragma unroll
    for (int mt = 0; mt < 4; mt++) {
        #pragma unroll
        for (int nt = 0; nt < 4; nt++) {
            int row = m0 + wm * 64 + mt * 16 + (lane >> 2);
            int col = n0 + wn * 32 + nt * 8 + (lane & 3) * 2;
            #pragma unroll
            for (int t = 0; t < 4; t++) {
                int gm = row + (t >> 1) * 8;
                int gn = col + (t & 1);
                if (gm >= M || gn >= N) continue;
                float vv = c[mt][nt][t] * alpha;
                if (bias) vv += bias[gn];
                if (act == 1) vv = 0.5f * vv * (1.f + erff(vv * 0.70710678118654752f));
                size_t ci = (size_t)gm * ldc + gn;
                if (accum) vv += C[ci];
                C[ci] = vv;
            }
        }
    }
}

// ---------------- elementwise / norm kernels ----------------
__global__ void rmsnorm_kernel(const float* __restrict__ x, const float* __restrict__ w,
                               float* __restrict__ out) {
    size_t row = blockIdx.x;
    const float* xr = x + row * D_;
    float* o = out + row * D_;
    float s = 0.f;
    for (int i = threadIdx.x; i < D_; i += blockDim.x) { float v = xr[i]; s += v * v; }
    s = blockReduceSum(s);
    float inv = rsqrtf(s / (float)D_ + EPS_);
    for (int i = threadIdx.x; i < D_; i += blockDim.x) o[i] = xr[i] * inv * w[i];
}

__global__ void layernorm_kernel(float* __restrict__ x, const float* __restrict__ g,
                                 const float* __restrict__ b) {
    size_t row = blockIdx.x;
    float* xr = x + row * D_;
    float s = 0.f;
    for (int i = threadIdx.x; i < D_; i += blockDim.x) s += xr[i];
    s = blockReduceSum(s);
    float mu = s / (float)D_;
    float s2 = 0.f;
    for (int i = threadIdx.x; i < D_; i += blockDim.x) { float d = xr[i] - mu; s2 += d * d; }
    s2 = blockReduceSum(s2);
    float inv = rsqrtf(s2 / (float)D_ + EPS_);
    for (int i = threadIdx.x; i < D_; i += blockDim.x)
        xr[i] = (xr[i] - mu) * inv * g[i] + b[i];
}

__global__ void embed_kernel(const int* __restrict__ ids, const int* __restrict__ pos,
                             const float* __restrict__ tok_emb, const float* __restrict__ spec,
                             float* __restrict__ h) {
    int bs = blockIdx.x;
    int b = bs / S_, s = bs % S_;
    int p = pos[b];
    const float* src;
    if (s >= p && s < p + K_) src = spec + ((size_t)b * K_ + (s - p)) * D_;
    else                      src = tok_emb + (size_t)ids[bs] * D_;
    float* dst = h + (size_t)bs * D_;
    for (int i = threadIdx.x; i < D_; i += blockDim.x) dst[i] = src[i];
}

__global__ void rope_kernel(float* __restrict__ x, int nheads, size_t total) {
    size_t idx = (size_t)blockIdx.x * blockDim.x + threadIdx.x;
    if (idx >= total) return;
    int i = (int)(idx & (HD_ / 2 - 1));
    size_t t = idx >> 6;                 // / (HD/2)
    int s = (int)((t / nheads) % S_);
    float freq = expf(((float)(2 * i) / (float)HD_) * -9.210340371976184f); // -ln(1e4)
    float ang = (float)s * freq;
    float sn, cs; sincosf(ang, &sn, &cs);
    size_t off = (t << 7) + 2 * i;       // t*HD + 2i
    float xr = x[off], xi = x[off + 1];
    x[off]     = xr * cs - xi * sn;
    x[off + 1] = xr * sn + xi * cs;
}

__global__ void softmax_causal_kernel(float* __restrict__ sc) {
    size_t row = blockIdx.x;             // (b*NH + h)*S + q
    int q = (int)(row % S_);
    float* r = sc + row * (size_t)S_;
    int n = q + 1;
    float mx = -3.4e38f;
    for (int j = threadIdx.x; j < n; j += blockDim.x) mx = fmaxf(mx, r[j]);
    mx = blockReduceMax(mx);
    float sum = 0.f;
    for (int j = threadIdx.x; j < n; j += blockDim.x) {
        float e = expf(r[j] - mx);
        r[j] = e; sum += e;
    }
    sum = blockReduceSum(sum);
    float inv = 1.f / sum;
    for (int j = threadIdx.x; j < n; j += blockDim.x) r[j] *= inv;
    for (int j = n + threadIdx.x; j < S_; j += blockDim.x) r[j] = 0.f;
}

__global__ void silu_mul_kernel(float* __restrict__ a, const float* __restrict__ c, size_t n) {
    size_t i = (size_t)blockIdx.x * blockDim.x + threadIdx.x;
    if (i >= n) return;
    float xv = a[i];
    a[i] = (xv / (1.f + expf(-xv))) * c[i];
}

// ---------------- host side ----------------
static inline void gemm_nb(const float* A, const float* Bm, float* C, const float* bias,
                           int M, int N, int Kd, int lda, int ldb, int ldc,
                           float alpha, int act, int accum) {
    dim3 grid((N + BN - 1) / BN, (M + BM - 1) / BM, 1);
    gemm_kernel<<<grid, 256>>>(A, Bm, C, bias, M, N, Kd, lda, ldb, ldc,
                               0, 0, 0, 0, 0, 0, 1, 1, alpha, act, accum, 0);
}

extern "C" void kernel_launch(void* const* d_in, const int* in_sizes, int n_in,
                              void* d_out, int out_size) {
    const int*   input_ids = (const int*)  d_in[0];
    const float* spectra   = (const float*)d_in[1];
    const int*   spos      = (const int*)  d_in[2];
    const float* proj_w1   = (const float*)d_in[3];
    const float* proj_b1   = (const float*)d_in[4];
    const float* proj_w2   = (const float*)d_in[5];
    const float* proj_b2   = (const float*)d_in[6];
    const float* proj_ln_g = (const float*)d_in[7];
    const float* proj_ln_b = (const float*)d_in[8];
    const float* tok_emb   = (const float*)d_in[9];
    const float* attn_norm = (const float*)d_in[10];
    const float* wq        = (const float*)d_in[11];
    const float* wk        = (const float*)d_in[12];
    const float* wv        = (const float*)d_in[13];
    const float* wo        = (const float*)d_in[14];
    const float* ffn_norm  = (const float*)d_in[15];
    const float* w1        = (const float*)d_in[16];
    const float* w3        = (const float*)d_in[17];
    const float* w2        = (const float*)d_in[18];
    const float* norm_w    = (const float*)d_in[19];
    const float* out_w     = (const float*)d_in[20];
    float* out = (float*)d_out;

    float *h, *x, *q, *k, *v, *attn, *sc, *f1, *f3, *h1, *spec;
    cudaGetSymbolAddress((void**)&h,    g_h);
    cudaGetSymbolAddress((void**)&x,    g_x);
    cudaGetSymbolAddress((void**)&q,    g_q);
    cudaGetSymbolAddress((void**)&k,    g_k);
    cudaGetSymbolAddress((void**)&v,    g_v);
    cudaGetSymbolAddress((void**)&attn, g_attn);
    cudaGetSymbolAddress((void**)&sc,   g_sc);
    cudaGetSymbolAddress((void**)&f1,   g_f1);
    cudaGetSymbolAddress((void**)&f3,   g_f3);
    cudaGetSymbolAddress((void**)&h1,   g_h1);
    cudaGetSymbolAddress((void**)&spec, g_spec);

    // ---- spectral projection: gelu(spectra@W1+b1) @ W2 + b2, then LayerNorm ----
    gemm_nb(spectra, proj_w1, h1, proj_b1, B_, HID_, LAT_, LAT_, HID_, HID_, 1.f, 1, 0);
    gemm_nb(h1, proj_w2, spec, proj_b2, B_, K_*D_, HID_, HID_, K_*D_, K_*D_, 1.f, 0, 0);
    layernorm_kernel<<<B_*K_, 256>>>(spec, proj_ln_g, proj_ln_b);

    // ---- embedding + spectral token scatter ----
    embed_kernel<<<B_*S_, 256>>>(input_ids, spos, tok_emb, spec, h);

    const float inv_sqrt_hd = 0.08838834764831845f;

    for (int l = 0; l < 2; l++) {
        const float* Wq = wq + (size_t)l * D_ * (NH_ * HD_);
        const float* Wk = wk + (size_t)l * D_ * (NKV_ * HD_);
        const float* Wv = wv + (size_t)l * D_ * (NKV_ * HD_);
        const float* Wo = wo + (size_t)l * (NH_ * HD_) * D_;
        const float* W1 = w1 + (size_t)l * D_ * FFN_;
        const float* W3 = w3 + (size_t)l * D_ * FFN_;
        const float* W2 = w2 + (size_t)l * FFN_ * D_;

        rmsnorm_kernel<<<B_*S_, 256>>>(h, attn_norm + (size_t)l * D_, x);

        gemm_nb(x, Wq, q, nullptr, B_*S_, NH_*HD_,  D_, D_, NH_*HD_,  NH_*HD_,  1.f, 0, 0);
        gemm_nb(x, Wk, k, nullptr, B_*S_, NKV_*HD_, D_, D_, NKV_*HD_, NKV_*HD_, 1.f, 0, 0);
        gemm_nb(x, Wv, v, nullptr, B_*S_, NKV_*HD_, D_, D_, NKV_*HD_, NKV_*HD_, 1.f, 0, 0);

        {
            size_t np = (size_t)B_ * S_ * NH_ * (HD_ / 2);
            rope_kernel<<<(unsigned)((np + 255) / 256), 256>>>(q, NH_, np);
            np = (size_t)B_ * S_ * NKV_ * (HD_ / 2);
            rope_kernel<<<(unsigned)((np + 255) / 256), 256>>>(k, NKV_, np);
        }

        // scores[b,h] = (1/sqrt(HD)) * Q_bh (S x HD) @ K_bh^T
        {
            dim3 grid(S_/BN, S_/BM, B_*NH_);
            gemm_kernel<<<grid, 256>>>(q, k, sc, nullptr,
                S_, S_, HD_,
                D_, NKV_*HD_, S_,
                (long long)S_*D_,        (long long)HD_,
                (long long)S_*NKV_*HD_,  (long long)HD_,
                (long long)NH_*S_*S_,    (long long)S_*S_,
                NH_, NREP_, inv_sqrt_hd, 0, 0, 1);
        }

        softmax_causal_kernel<<<B_*NH_*S_, 128>>>(sc);

        // attn[b,:,h,:] = P_bh (S x S) @ V_bh (S x HD)
        {
            dim3 grid(HD_/BN, S_/BM, B_*NH_);
            gemm_kernel<<<grid, 256>>>(sc, v, attn, nullptr,
                S_, HD_, S_,
                S_, NKV_*HD_, D_,
                (long long)NH_*S_*S_,    (long long)S_*S_,
                (long long)S_*NKV_*HD_,  (long long)HD_,
                (long long)S_*D_,        (long long)HD_,
                NH_, NREP_, 1.f, 0, 0, 0);
        }

        // h += attn @ Wo
        gemm_nb(attn, Wo, h, nullptr, B_*S_, D_, D_, D_, D_, D_, 1.f, 0, 1);

        // FFN
        rmsnorm_kernel<<<B_*S_, 256>>>(h, ffn_norm + (size_t)l * D_, x);
        gemm_nb(x, W1, f1, nullptr, B_*S_, FFN_, D_, D_, FFN_, FFN_, 1.f, 0, 0);
        gemm_nb(x, W3, f3, nullptr, B_*S_, FFN_, D_, D_, FFN_, FFN_, 1.f, 0, 0);
        {
            size_t n = (size_t)B_ * S_ * FFN_;
            silu_mul_kernel<<<(unsigned)((n + 255) / 256), 256>>>(f1, f3, n);
        }
        // h += (silu(g1)*g3) @ W2
        gemm_nb(f1, W2, h, nullptr, B_*S_, D_, FFN_, FFN_, D_, D_, 1.f, 0, 1);
    }

    // ---- final norm + logits ----
    rmsnorm_kernel<<<B_*S_, 256>>>(h, norm_w, x);
    gemm_nb(x, out_w, out, nullptr, B_*S_, V_, D_, D_, V_, V_, 1.f, 0, 0);
}